// round 16
// baseline (speedup 1.0000x reference)
#include <cuda_runtime.h>
#include <cuda_bf16.h>

#define NN 50000
#define KK 17
#define DIN 128
#define DOUT 64

// Scratch for projected features xp = x @ W : [N, 64] fp32 = 12.8 MB (fits in L2)
__device__ float g_xp[(size_t)NN * DOUT];

// ---------------------------------------------------------------------------
// Kernel 1: xp = x @ W (fp32). R4 version — at the scalar-FFMA roof (~21.3us).
// ---------------------------------------------------------------------------
__global__ void __launch_bounds__(256) gemm_kernel(
    const float* __restrict__ x, const float* __restrict__ wm)
{
    __shared__ float xs[128][32];
    __shared__ float ws[32][64];

    const int tid  = threadIdx.x;
    const int row0 = blockIdx.x * 128;
    const int c0   = (tid & 15) * 4;
    const int r0   = (tid >> 4) * 8;

    float acc[8][4];
#pragma unroll
    for (int i = 0; i < 8; i++)
#pragma unroll
        for (int j = 0; j < 4; j++) acc[i][j] = 0.f;

    for (int k0 = 0; k0 < DIN; k0 += 32) {
#pragma unroll
        for (int i = 0; i < 4; i++) {
            const int f4 = tid + 256 * i;
            const int r  = f4 >> 3;
            const int cc = (f4 & 7) * 4;
            int gr = row0 + r;
            if (gr > NN - 1) gr = NN - 1;
            const float4 v = *(const float4*)(x + (size_t)gr * DIN + k0 + cc);
            *(float4*)&xs[r][cc] = v;
        }
#pragma unroll
        for (int i = 0; i < 2; i++) {
            const int f4 = tid + 256 * i;
            const int r  = f4 >> 4;
            const int cc = (f4 & 15) * 4;
            const float4 v = *(const float4*)(wm + (size_t)(k0 + r) * DOUT + cc);
            *(float4*)&ws[r][cc] = v;
        }
        __syncthreads();

#pragma unroll
        for (int kk = 0; kk < 32; kk += 2) {
            const float4 w0 = *(const float4*)&ws[kk][c0];
            const float4 w1 = *(const float4*)&ws[kk + 1][c0];
#pragma unroll
            for (int i = 0; i < 8; i++) {
                const float2 xv = *(const float2*)&xs[r0 + i][kk];
                acc[i][0] += xv.x * w0.x;
                acc[i][1] += xv.x * w0.y;
                acc[i][2] += xv.x * w0.z;
                acc[i][3] += xv.x * w0.w;
                acc[i][0] += xv.y * w1.x;
                acc[i][1] += xv.y * w1.y;
                acc[i][2] += xv.y * w1.z;
                acc[i][3] += xv.y * w1.w;
            }
        }
        __syncthreads();
    }

#pragma unroll
    for (int i = 0; i < 8; i++) {
        const int gr = row0 + r0 + i;
        if (gr < NN) {
            float4 v;
            v.x = acc[i][0]; v.y = acc[i][1]; v.z = acc[i][2]; v.w = acc[i][3];
            *(float4*)&g_xp[(size_t)gr * DOUT + c0] = v;
        }
    }
}

// ---------------------------------------------------------------------------
// Kernel 2: weighted per-dim median — ONE (node, dim) per thread for max
// occupancy (17 live keys -> ~32 regs), with the R15 alu-diet:
//  * embed: low mantissa byte <- j<<2 via 1 PRMT (<=255-ulp perturbation)
//  * sort: Green's 60-CE 16-sorter + 16-CE serial insertion, FMNMX only
//  * weight recovery: addr = PRMT(smem_base, key) into 256B-aligned rows
//  * walk: all-fma-pipe (fma.rn.sat exact indicator + telescoped median)
// ---------------------------------------------------------------------------
__device__ __forceinline__ float fmasat(float a, float b, float c) {
    float d;
    asm("fma.rn.sat.f32 %0, %1, %2, %3;" : "=f"(d) : "f"(a), "f"(b), "f"(c));
    return d;
}

#define CE(A, B) do {                      \
    const float ka_ = k##A, kb_ = k##B;    \
    k##A = fminf(ka_, kb_);                \
    k##B = fmaxf(ka_, kb_);                \
} while (0)

__global__ void __launch_bounds__(256) median_kernel(
    const int*   __restrict__ col,
    const float* __restrict__ ew,
    const float* __restrict__ bias,
    float*       __restrict__ out)
{
    __shared__ __align__(256) float swt[4][64];   // 256B per node row
    __shared__ int soff[4][KK];

    const int tid   = threadIdx.x;
    const int local = tid >> 6;          // node within block (0..3)
    const int d     = tid & 63;          // feature dim
    const int node  = blockIdx.x * 4 + local;

    if (d < KK) {
        swt[local][d]  = ew[node * KK + d];
        soff[local][d] = col[node * KK + d] * DOUT;
    }
    __syncthreads();

    const float* __restrict__ xpd = g_xp + d;
    const unsigned sb = (unsigned)__cvta_generic_to_shared(&swt[local][0]);

    // load values; embed j<<2 into low mantissa byte (1 PRMT each)
#define LOADJ(J) float k##J = __uint_as_float(                                 \
        __byte_perm(__float_as_uint(__ldg(xpd + soff[local][J])),              \
                    (J) << 2, 0x3214));
    LOADJ(0)  LOADJ(1)  LOADJ(2)  LOADJ(3)  LOADJ(4)  LOADJ(5)
    LOADJ(6)  LOADJ(7)  LOADJ(8)  LOADJ(9)  LOADJ(10) LOADJ(11)
    LOADJ(12) LOADJ(13) LOADJ(14) LOADJ(15) LOADJ(16)
#undef LOADJ

    const float* wl = swt[local];
    const float total =
        ((wl[0] + wl[1]) + (wl[2] + wl[3])) + ((wl[4] + wl[5]) + (wl[6] + wl[7])) +
        ((wl[8] + wl[9]) + (wl[10] + wl[11])) +
        ((wl[12] + wl[13]) + (wl[14] + wl[15])) + wl[16];
    // hfB = (0.5*total) * 2^40 = total * 2^39 (exact power-of-2 scale)
    const float hfB = total * 549755813888.0f;

    // --- Green's 16-element 60-CE sorting network on wires 0..15 ---
    CE(0,1);  CE(2,3);  CE(4,5);  CE(6,7);
    CE(8,9);  CE(10,11); CE(12,13); CE(14,15);

    CE(0,2);  CE(1,3);  CE(4,6);  CE(5,7);
    CE(8,10); CE(9,11); CE(12,14); CE(13,15);

    CE(0,4);  CE(1,5);  CE(2,6);  CE(3,7);
    CE(8,12); CE(9,13); CE(10,14); CE(11,15);

    CE(0,8);  CE(1,9);  CE(2,10); CE(3,11);
    CE(4,12); CE(5,13); CE(6,14); CE(7,15);

    CE(5,10); CE(6,9);  CE(3,12); CE(13,14);
    CE(7,11); CE(1,2);  CE(4,8);

    CE(1,4);  CE(7,13); CE(2,8);  CE(11,14);

    CE(2,4);  CE(5,6);  CE(9,10); CE(11,13);

    CE(3,8);  CE(7,12);

    CE(6,8);  CE(10,12); CE(3,5); CE(7,9);

    CE(3,4);  CE(5,6);  CE(7,8);  CE(9,10); CE(11,12);

    CE(6,7);  CE(8,9);

    // --- serial insertion of element 16 into the sorted 0..15 ---
    CE(15,16); CE(14,15); CE(13,14); CE(12,13);
    CE(11,12); CE(10,11); CE(9,10);  CE(8,9);
    CE(7,8);   CE(6,7);   CE(5,6);   CE(4,5);
    CE(3,4);   CE(2,3);   CE(1,2);   CE(0,1);

    // --- recover sorted weights: addr = PRMT(base, key); rows 256B-aligned ---
#define SWJ(J)                                                                 \
    float sw##J;                                                               \
    {                                                                          \
        const unsigned a_ = __byte_perm(sb, __float_as_uint(k##J), 0x3214);    \
        asm("ld.shared.b32 %0, [%1];" : "=f"(sw##J) : "r"(a_));                \
    }
    SWJ(0)  SWJ(1)  SWJ(2)  SWJ(3)  SWJ(4)  SWJ(5)  SWJ(6)  SWJ(7)  SWJ(8)
    SWJ(9)  SWJ(10) SWJ(11) SWJ(12) SWJ(13) SWJ(14) SWJ(15) SWJ(16)
#undef SWJ

    // --- all-fma walk: ind = exact [cum < hf]; med telescopes to k_c ---
    float cum = sw0;
    float med = k0;
#define STEP(J, JN) {                                       \
    const float i_ = fmasat(cum, -1099511627776.0f, hfB);   \
    med  = __fmaf_rn(i_, k##JN - k##J, med);                \
    cum += sw##JN; }
    STEP(0,1)   STEP(1,2)   STEP(2,3)   STEP(3,4)
    STEP(4,5)   STEP(5,6)   STEP(6,7)   STEP(7,8)
    STEP(8,9)   STEP(9,10)  STEP(10,11) STEP(11,12)
    STEP(12,13) STEP(13,14) STEP(14,15) STEP(15,16)
#undef STEP

    out[(size_t)node * DOUT + d] = total * med + __ldg(&bias[d]);
}

// ---------------------------------------------------------------------------
// Inputs: x[N,128] f32, edge_index[2,E] i32, edge_weight[E] f32,
//         weight[128,64] f32, bias[64] f32. Output: [N,64] f32.
// ---------------------------------------------------------------------------
extern "C" void kernel_launch(void* const* d_in, const int* in_sizes, int n_in,
                              void* d_out, int out_size)
{
    const float* x    = (const float*)d_in[0];
    const int*   ei   = (const int*)  d_in[1];
    const float* ew   = (const float*)d_in[2];
    const float* wm   = (const float*)d_in[3];
    const float* bias = (const float*)d_in[4];
    float*       out  = (float*)d_out;

    const int E = in_sizes[1] / 2;
    const int* col = ei + E;

    gemm_kernel<<<(NN + 127) / 128, 256>>>(x, wm);
    median_kernel<<<NN / 4, 256>>>(col, ew, bias, out);   // 4 nodes per block
}

// round 17
// speedup vs baseline: 1.6990x; 1.6990x over previous
#include <cuda_runtime.h>
#include <cuda_bf16.h>

#define NN 50000
#define KK 17
#define DIN 128
#define DOUT 64

// Scratch for projected features xp = x @ W : [N, 64] fp32 = 12.8 MB (fits in L2)
__device__ float g_xp[(size_t)NN * DOUT];

// ---------------------------------------------------------------------------
// Kernel 1: xp = x @ W (fp32). R4 version — at the scalar-FFMA roof (~21.3us).
// ---------------------------------------------------------------------------
__global__ void __launch_bounds__(256) gemm_kernel(
    const float* __restrict__ x, const float* __restrict__ wm)
{
    __shared__ float xs[128][32];
    __shared__ float ws[32][64];

    const int tid  = threadIdx.x;
    const int row0 = blockIdx.x * 128;
    const int c0   = (tid & 15) * 4;
    const int r0   = (tid >> 4) * 8;

    float acc[8][4];
#pragma unroll
    for (int i = 0; i < 8; i++)
#pragma unroll
        for (int j = 0; j < 4; j++) acc[i][j] = 0.f;

    for (int k0 = 0; k0 < DIN; k0 += 32) {
#pragma unroll
        for (int i = 0; i < 4; i++) {
            const int f4 = tid + 256 * i;
            const int r  = f4 >> 3;
            const int cc = (f4 & 7) * 4;
            int gr = row0 + r;
            if (gr > NN - 1) gr = NN - 1;
            const float4 v = *(const float4*)(x + (size_t)gr * DIN + k0 + cc);
            *(float4*)&xs[r][cc] = v;
        }
#pragma unroll
        for (int i = 0; i < 2; i++) {
            const int f4 = tid + 256 * i;
            const int r  = f4 >> 4;
            const int cc = (f4 & 15) * 4;
            const float4 v = *(const float4*)(wm + (size_t)(k0 + r) * DOUT + cc);
            *(float4*)&ws[r][cc] = v;
        }
        __syncthreads();

#pragma unroll
        for (int kk = 0; kk < 32; kk += 2) {
            const float4 w0 = *(const float4*)&ws[kk][c0];
            const float4 w1 = *(const float4*)&ws[kk + 1][c0];
#pragma unroll
            for (int i = 0; i < 8; i++) {
                const float2 xv = *(const float2*)&xs[r0 + i][kk];
                acc[i][0] += xv.x * w0.x;
                acc[i][1] += xv.x * w0.y;
                acc[i][2] += xv.x * w0.z;
                acc[i][3] += xv.x * w0.w;
                acc[i][0] += xv.y * w1.x;
                acc[i][1] += xv.y * w1.y;
                acc[i][2] += xv.y * w1.z;
                acc[i][3] += xv.y * w1.w;
            }
        }
        __syncthreads();
    }

#pragma unroll
    for (int i = 0; i < 8; i++) {
        const int gr = row0 + r0 + i;
        if (gr < NN) {
            float4 v;
            v.x = acc[i][0]; v.y = acc[i][1]; v.z = acc[i][2]; v.w = acc[i][3];
            *(float4*)&g_xp[(size_t)gr * DOUT + c0] = v;
        }
    }
}

// ---------------------------------------------------------------------------
// Kernel 2: weighted per-dim median, dims (2*d0, 2*d0+1) of one node per
// thread (2-way ILP, R15 structure) with VECTORIZED gather: one LDG.64 per
// neighbor serves both dims (halves LDG count + address math + L1 requests).
//  * embed: low mantissa byte <- j<<2 via 1 PRMT (<=255-ulp perturbation)
//  * sort: Green's 60-CE 16-sorter + 16-CE serial insertion, FMNMX only
//  * weight recovery: addr = PRMT(smem_base, key) into 256B-aligned rows
//  * walk: all-fma-pipe (fma.rn.sat exact indicator + telescoped median)
//  * output: one STG.64, bias one LDG.64
// ---------------------------------------------------------------------------
__device__ __forceinline__ float fmasat(float a, float b, float c) {
    float d;
    asm("fma.rn.sat.f32 %0, %1, %2, %3;" : "=f"(d) : "f"(a), "f"(b), "f"(c));
    return d;
}

#define CE2(A, B) do {                         \
    const float a0_ = kA##A, b0_ = kA##B;      \
    const float a1_ = kB##A, b1_ = kB##B;      \
    kA##A = fminf(a0_, b0_);                   \
    kB##A = fminf(a1_, b1_);                   \
    kA##B = fmaxf(a0_, b0_);                   \
    kB##B = fmaxf(a1_, b1_);                   \
} while (0)

__global__ void __launch_bounds__(256) median_kernel(
    const int*   __restrict__ col,
    const float* __restrict__ ew,
    const float* __restrict__ bias,
    float*       __restrict__ out)
{
    __shared__ __align__(256) float swt[8][64];   // 256B per node row
    __shared__ int soff[8][KK];

    const int tid  = threadIdx.x;
    const int nl   = tid >> 5;          // node within block (0..7)
    const int d0   = tid & 31;          // dim pair: (2*d0, 2*d0+1)
    const int node = blockIdx.x * 8 + nl;

    if (d0 < KK) {
        swt[nl][d0]  = ew[node * KK + d0];
        soff[nl][d0] = col[node * KK + d0] * DOUT;
    }
    __syncthreads();

    const float* __restrict__ xpd = g_xp + 2 * d0;
    const unsigned sb = (unsigned)__cvta_generic_to_shared(&swt[nl][0]);

    // one LDG.64 per neighbor: loads dims 2*d0 and 2*d0+1 together;
    // embed j<<2 into low mantissa byte (1 PRMT per half)
#define LOADJ(J)                                                               \
    float kA##J, kB##J;                                                        \
    {                                                                          \
        const float2 v_ = __ldg((const float2*)(xpd + soff[nl][J]));           \
        kA##J = __uint_as_float(                                               \
            __byte_perm(__float_as_uint(v_.x), (J) << 2, 0x3214));             \
        kB##J = __uint_as_float(                                               \
            __byte_perm(__float_as_uint(v_.y), (J) << 2, 0x3214));             \
    }
    LOADJ(0)  LOADJ(1)  LOADJ(2)  LOADJ(3)  LOADJ(4)  LOADJ(5)
    LOADJ(6)  LOADJ(7)  LOADJ(8)  LOADJ(9)  LOADJ(10) LOADJ(11)
    LOADJ(12) LOADJ(13) LOADJ(14) LOADJ(15) LOADJ(16)
#undef LOADJ

    const float* wl = swt[nl];
    const float total =
        ((wl[0] + wl[1]) + (wl[2] + wl[3])) + ((wl[4] + wl[5]) + (wl[6] + wl[7])) +
        ((wl[8] + wl[9]) + (wl[10] + wl[11])) +
        ((wl[12] + wl[13]) + (wl[14] + wl[15])) + wl[16];
    // hfB = (0.5*total) * 2^40 = total * 2^39 (exact power-of-2 scale)
    const float hfB = total * 549755813888.0f;

    // --- Green's 16-element 60-CE sorting network on wires 0..15 (x2 ILP) ---
    CE2(0,1);  CE2(2,3);  CE2(4,5);  CE2(6,7);
    CE2(8,9);  CE2(10,11); CE2(12,13); CE2(14,15);

    CE2(0,2);  CE2(1,3);  CE2(4,6);  CE2(5,7);
    CE2(8,10); CE2(9,11); CE2(12,14); CE2(13,15);

    CE2(0,4);  CE2(1,5);  CE2(2,6);  CE2(3,7);
    CE2(8,12); CE2(9,13); CE2(10,14); CE2(11,15);

    CE2(0,8);  CE2(1,9);  CE2(2,10); CE2(3,11);
    CE2(4,12); CE2(5,13); CE2(6,14); CE2(7,15);

    CE2(5,10); CE2(6,9);  CE2(3,12); CE2(13,14);
    CE2(7,11); CE2(1,2);  CE2(4,8);

    CE2(1,4);  CE2(7,13); CE2(2,8);  CE2(11,14);

    CE2(2,4);  CE2(5,6);  CE2(9,10); CE2(11,13);

    CE2(3,8);  CE2(7,12);

    CE2(6,8);  CE2(10,12); CE2(3,5); CE2(7,9);

    CE2(3,4);  CE2(5,6);  CE2(7,8);  CE2(9,10); CE2(11,12);

    CE2(6,7);  CE2(8,9);

    // --- serial insertion of element 16 (two chains interleave for ILP) ---
    CE2(15,16); CE2(14,15); CE2(13,14); CE2(12,13);
    CE2(11,12); CE2(10,11); CE2(9,10);  CE2(8,9);
    CE2(7,8);   CE2(6,7);   CE2(5,6);   CE2(4,5);
    CE2(3,4);   CE2(2,3);   CE2(1,2);   CE2(0,1);

    // --- recover sorted weights: addr = PRMT(base, key); rows 256B-aligned ---
#define SWJ(J)                                                                 \
    float swA##J, swB##J;                                                      \
    {                                                                          \
        const unsigned aA = __byte_perm(sb, __float_as_uint(kA##J), 0x3214);   \
        const unsigned aB = __byte_perm(sb, __float_as_uint(kB##J), 0x3214);   \
        asm("ld.shared.b32 %0, [%1];" : "=f"(swA##J) : "r"(aA));               \
        asm("ld.shared.b32 %0, [%1];" : "=f"(swB##J) : "r"(aB));               \
    }
    SWJ(0)  SWJ(1)  SWJ(2)  SWJ(3)  SWJ(4)  SWJ(5)  SWJ(6)  SWJ(7)  SWJ(8)
    SWJ(9)  SWJ(10) SWJ(11) SWJ(12) SWJ(13) SWJ(14) SWJ(15) SWJ(16)
#undef SWJ

    // --- all-fma walk: ind = exact [cum < hf]; med telescopes to k_c ---
    float cumA = swA0, cumB = swB0;
    float medA = kA0,  medB = kB0;
#define STEP(J, JN) {                                         \
    const float iA = fmasat(cumA, -1099511627776.0f, hfB);    \
    const float iB = fmasat(cumB, -1099511627776.0f, hfB);    \
    medA = __fmaf_rn(iA, kA##JN - kA##J, medA);               \
    medB = __fmaf_rn(iB, kB##JN - kB##J, medB);               \
    cumA += swA##JN;                                          \
    cumB += swB##JN; }
    STEP(0,1)   STEP(1,2)   STEP(2,3)   STEP(3,4)
    STEP(4,5)   STEP(5,6)   STEP(6,7)   STEP(7,8)
    STEP(8,9)   STEP(9,10)  STEP(10,11) STEP(11,12)
    STEP(12,13) STEP(13,14) STEP(14,15) STEP(15,16)
#undef STEP

    const float2 b2 = __ldg((const float2*)(bias + 2 * d0));
    float2 o;
    o.x = total * medA + b2.x;
    o.y = total * medB + b2.y;
    *(float2*)(out + (size_t)node * DOUT + 2 * d0) = o;
}

// ---------------------------------------------------------------------------
// Inputs: x[N,128] f32, edge_index[2,E] i32, edge_weight[E] f32,
//         weight[128,64] f32, bias[64] f32. Output: [N,64] f32.
// ---------------------------------------------------------------------------
extern "C" void kernel_launch(void* const* d_in, const int* in_sizes, int n_in,
                              void* d_out, int out_size)
{
    const float* x    = (const float*)d_in[0];
    const int*   ei   = (const int*)  d_in[1];
    const float* ew   = (const float*)d_in[2];
    const float* wm   = (const float*)d_in[3];
    const float* bias = (const float*)d_in[4];
    float*       out  = (float*)d_out;

    const int E = in_sizes[1] / 2;
    const int* col = ei + E;

    gemm_kernel<<<(NN + 127) / 128, 256>>>(x, wm);
    median_kernel<<<NN / 8, 256>>>(col, ew, bias, out);   // 8 nodes per block
}